// round 16
// baseline (speedup 1.0000x reference)
#include <cuda_runtime.h>
#include <cuda_fp16.h>
#include <cstdint>

// Problem constants
#define B_    64
#define CIN_  64
#define T_    4096
#define F_    128
#define K_    64
#define TOUT_ 4033
#define NPAIR 64

// ---- K1 (HMMA spatial GEMM) ----
#define T1_   128
#define NT1_  32                  // 4096 / 128
#define XFS   132                 // x_s fp32 row stride (floats)
#define HS    72                  // fp16 tile row stride (halves); 144B, 16B-aligned
#define S1_XF 0                   // x_s fp32: 64*132*4 = 33792 B
#define S1_W  33792               // Ws fp16: 128*72*2 = 18432 B
#define S1_X  52224               // Xs fp16: 128*72*2 = 18432 B
#define S1_BYTES 70656

// ---- K2 (temporal, HFMA2) ----
#define T2_   256
#define SPAN2 320                 // T2_ + K_
#define NT2_  16
#define NCTA2_ (NT2_ * 2 * B_)    // 2048
#define YHS   321                 // yil row stride (half2): mod32==1 -> CF LDS.32
#define CWHS  65                  // cw row stride (half2):  mod32==1 -> CF
// byte offsets
#define O2_Y    0                 // 32*321*4 = 41088
#define O2_CW   41088             // 32*65*4  = 8320
#define O2_SSQ  49408             // 320*4 = 1280
#define O2_INV  50688             // 256*4 = 1024
#define O2_SACC 51712             // 64*4 = 256
#define SM2_BYTES 51968           // -> 4 CTAs/SM

__device__ __align__(16) __half2 g_yh[(size_t)B_ * NPAIR * T_];  // [b][pair][t]
__device__ float    g_ssq[B_ * T_];
__device__ float    g_acc[B_ * F_];      // zero-init; reset by last CTA
__device__ unsigned g_count;             // zero-init; reset by last CTA

__device__ __forceinline__ uint32_t smem_u32(const void* p) {
    uint32_t a;
    asm("{ .reg .u64 t; cvta.to.shared.u64 t, %1; cvt.u32.u64 %0, t; }"
        : "=r"(a) : "l"(p));
    return a;
}

// ---------------------------------------------------------------------------
// K1: spatial GEMM on HMMA (mma.sync m16n8k16 f16 -> f32 acc) + exact ssq.
// grid (NT1_, B_), 256 threads. No OOB (32*128 = 4096 exact). (R15, unchanged)
// ---------------------------------------------------------------------------
__global__ __launch_bounds__(256, 2)
void k1_spatial(const float* __restrict__ x,
                const float* __restrict__ spat_w) {
    extern __shared__ char smem[];
    float*   x_s = (float*)(smem + S1_XF);     // [64 c][XFS]
    __half2* ws2 = (__half2*)(smem + S1_W);    // [128 f][HS/2 half2]
    __half2* xs2 = (__half2*)(smem + S1_X);    // [128 t][HS/2 half2]
    const uint32_t wsb = smem_u32(smem + S1_W);
    const uint32_t xsb = smem_u32(smem + S1_X);

    const int tid  = threadIdx.x;
    const int b    = blockIdx.y;
    const int t0g  = blockIdx.x * T1_;
    const int warp = tid >> 5;
    const int lane = tid & 31;

    // ---- stage x fp32 tile [64c][128t] (coalesced float4) ----
    #pragma unroll
    for (int r = 0; r < 8; r++) {
        int q = r * 256 + tid;
        int c = q >> 5, t4 = (q & 31) * 4;
        *(float4*)(x_s + c * XFS + t4) =
            *(const float4*)(x + (size_t)(b * CIN_ + c) * T_ + t0g + t4);
    }
    // ---- stage W fp16: ws[f][c] ----
    #pragma unroll
    for (int r = 0; r < 16; r++) {
        int idx = r * 256 + tid;
        int f = idx >> 5, cp = idx & 31;
        float2 v = ((const float2*)spat_w)[idx];
        ws2[f * (HS / 2) + cp] = __floats2half2_rn(v.x, v.y);
    }
    __syncthreads();

    // ---- exact fp32 ssq ----
    if (tid < T1_) {
        float s = 0.f;
        #pragma unroll 8
        for (int c = 0; c < CIN_; c++) {
            float v = x_s[c * XFS + tid];
            s += v * v;
        }
        g_ssq[b * T_ + t0g + tid] = s;
    }
    // ---- transpose x -> Xs fp16 [t][c] ----
    {
        int t = tid & 127, ch = tid >> 7;
        int c0 = 32 * ch;
        #pragma unroll
        for (int j = 0; j < 16; j++) {
            float v0 = x_s[(c0 + 2 * j)     * XFS + t];
            float v1 = x_s[(c0 + 2 * j + 1) * XFS + t];
            xs2[t * (HS / 2) + c0 / 2 + j] = __floats2half2_rn(v0, v1);
        }
    }
    __syncthreads();

    // ---- HMMA: warp owns 16 filters x 128 t ----
    const int m0 = 16 * warp;
    float d[16][4];
    #pragma unroll
    for (int nt = 0; nt < 16; nt++)
        #pragma unroll
        for (int i = 0; i < 4; i++) d[nt][i] = 0.f;

    const int a_off = (m0 + (lane & 15)) * HS + (lane >> 4) * 8;
    const int b_off = (8 * (lane >> 4) + (lane & 7)) * HS + 8 * ((lane >> 3) & 1);

    #pragma unroll
    for (int ks = 0; ks < 4; ks++) {
        uint32_t a0, a1, a2, a3;
        {
            uint32_t addr = wsb + 2 * (a_off + 16 * ks);
            asm volatile("ldmatrix.sync.aligned.m8n8.x4.shared.b16 {%0,%1,%2,%3}, [%4];"
                : "=r"(a0), "=r"(a1), "=r"(a2), "=r"(a3) : "r"(addr));
        }
        #pragma unroll
        for (int j = 0; j < 8; j++) {
            uint32_t b0, b1, b2, b3;
            uint32_t addr = xsb + 2 * (b_off + (16 * j) * HS + 16 * ks);
            asm volatile("ldmatrix.sync.aligned.m8n8.x4.shared.b16 {%0,%1,%2,%3}, [%4];"
                : "=r"(b0), "=r"(b1), "=r"(b2), "=r"(b3) : "r"(addr));
            asm volatile(
                "mma.sync.aligned.m16n8k16.row.col.f32.f16.f16.f32 "
                "{%0,%1,%2,%3}, {%4,%5,%6,%7}, {%8,%9}, {%0,%1,%2,%3};"
                : "+f"(d[2*j][0]), "+f"(d[2*j][1]), "+f"(d[2*j][2]), "+f"(d[2*j][3])
                : "r"(a0), "r"(a1), "r"(a2), "r"(a3), "r"(b0), "r"(b1));
            asm volatile(
                "mma.sync.aligned.m16n8k16.row.col.f32.f16.f16.f32 "
                "{%0,%1,%2,%3}, {%4,%5,%6,%7}, {%8,%9}, {%0,%1,%2,%3};"
                : "+f"(d[2*j+1][0]), "+f"(d[2*j+1][1]), "+f"(d[2*j+1][2]), "+f"(d[2*j+1][3])
                : "r"(a0), "r"(a1), "r"(a2), "r"(a3), "r"(b2), "r"(b3));
        }
    }

    // ---- epilogue: pair even/odd filters via shfl, write half2 y ----
    {
        const int gid  = lane >> 2;
        const int tid4 = lane & 3;
        const bool wr  = (gid & 1) == 0;
        const size_t ybase = (size_t)b * NPAIR * T_;
        const int Plo = 8 * warp + (gid >> 1);
        #pragma unroll
        for (int nt = 0; nt < 16; nt++) {
            float p0 = __shfl_xor_sync(0xffffffffu, d[nt][0], 4);
            float p1 = __shfl_xor_sync(0xffffffffu, d[nt][1], 4);
            float p2 = __shfl_xor_sync(0xffffffffu, d[nt][2], 4);
            float p3 = __shfl_xor_sync(0xffffffffu, d[nt][3], 4);
            if (wr) {
                int t = t0g + 8 * nt + 2 * tid4;
                __half2 h0 = __floats2half2_rn(d[nt][0], p0);
                __half2 h1 = __floats2half2_rn(d[nt][1], p1);
                __half2 h2 = __floats2half2_rn(d[nt][2], p2);
                __half2 h3 = __floats2half2_rn(d[nt][3], p3);
                float2 lo, hi;
                memcpy(&lo, &h0, 4); memcpy((char*)&lo + 4, &h1, 4);
                memcpy(&hi, &h2, 4); memcpy((char*)&hi + 4, &h3, 4);
                *(float2*)(g_yh + ybase + (size_t)Plo * T_ + t)       = lo;
                *(float2*)(g_yh + ybase + (size_t)(Plo + 4) * T_ + t) = hi;
            }
        }
    }
}

// ---------------------------------------------------------------------------
// K2: temporal conv in HFMA2 (dual fp16 accumulators) + reduction.
// grid (NT2_, 2, B_), 256 threads, 4 CTAs/SM.
// ---------------------------------------------------------------------------
__global__ __launch_bounds__(256, 4)
void k2_temporal(const float* __restrict__ conv_w,
                 const float* __restrict__ spat_w,
                 const float* __restrict__ weight,
                 const float* __restrict__ bias,
                 float* __restrict__ out) {
    extern __shared__ char sm2[];
    __half2* yilh = (__half2*)(sm2 + O2_Y);    // [32 pairs][YHS]
    __half2* cwh  = (__half2*)(sm2 + O2_CW);   // [32 pairs][CWHS]
    float*   ssqs = (float*)(sm2 + O2_SSQ);    // [320]
    float*   invn = (float*)(sm2 + O2_INV);    // [256]
    float*   sacc = (float*)(sm2 + O2_SACC);   // [64]
    __shared__ unsigned sflag;

    const int tid  = threadIdx.x;
    const int tile = blockIdx.x;
    const int h    = blockIdx.y;               // filter half (64 filters)
    const int b    = blockIdx.z;
    const int t0g  = tile * T2_;
    const int warp = tid >> 5;
    const int lane = tid & 31;

    if (tid < 64) sacc[tid] = 0.f;

    // ---- stage interleaved conv weights fp16: cwh[p][k] = (cw[2p][k], cw[2p+1][k])
    #pragma unroll
    for (int r = 0; r < 16; r++) {
        int idx = r * 256 + tid;               // 0..4095
        int fl = idx >> 6, k = idx & 63;
        float v = conv_w[(64 * h + fl) * K_ + k];
        ((__half*)cwh)[(fl >> 1) * (2 * CWHS) + 2 * k + (fl & 1)] = __float2half(v);
    }
    // ---- stage ssq (guarded) ----
    #pragma unroll
    for (int i = tid; i < SPAN2; i += 256) {
        int tg = t0g + i;
        ssqs[i] = (tg < T_) ? g_ssq[b * T_ + tg] : 0.f;
    }
    // ---- stage y tile raw half2 (warp-strided, guarded zero-fill) ----
    {
        const __half2* ysrc = g_yh + (size_t)(b * NPAIR + 32 * h) * T_ + t0g;
        const __half2 z2 = __float2half2_rn(0.f);
        #pragma unroll
        for (int p = warp; p < 32; p += 8) {
            const __half2* yp = ysrc + (size_t)p * T_;
            #pragma unroll
            for (int t = lane; t < SPAN2; t += 32)
                yilh[p * YHS + t] = (t0g + t < T_) ? yp[t] : z2;
        }
    }
    __syncthreads();

    // invn over the 256 outputs of this tile
    {
        float s = 0.f;
        #pragma unroll 8
        for (int k = 0; k < K_; k++) s += ssqs[tid + k];
        invn[tid] = ((t0g + tid) < TOUT_ && s > 0.f) ? rsqrtf(s) : 0.f;
    }
    __syncthreads();

    // ---- temporal conv: lane = pair; warp -> 32 t (2 chunks of 16) ----
    {
        const __half2* yr  = yilh + lane * YHS;
        const __half2* cwr = cwh + lane * CWHS;
        float pe = 0.f, po = 0.f;

        #pragma unroll
        for (int ch = 0; ch < 2; ch++) {
            const int t0 = 32 * warp + 16 * ch;

            __half2 ta[16], tb[16];            // dual accumulators (even/odd k)
            const __half2 z2 = __float2half2_rn(0.f);
            #pragma unroll
            for (int i = 0; i < 16; i++) { ta[i] = z2; tb[i] = z2; }

            __half2 w2h[16];
            #pragma unroll
            for (int i = 0; i < 16; i++) w2h[i] = yr[t0 + i];

            __half2 s = cwr[0];                // cw prefetch (1 k ahead)
            for (int ko = 0; ko < 4; ko++) {
                #pragma unroll
                for (int ku = 0; ku < 16; ku++) {
                    const int k = 16 * ko + ku;
                    __half2 sc = s;
                    s = cwr[k + 1];            // k=63 reads pad slot 64 (never used)
                    if ((ku & 1) == 0) {
                        #pragma unroll
                        for (int i = 0; i < 16; i++)
                            ta[i] = __hfma2(sc, w2h[(ku + i) & 15], ta[i]);
                    } else {
                        #pragma unroll
                        for (int i = 0; i < 16; i++)
                            tb[i] = __hfma2(sc, w2h[(ku + i) & 15], tb[i]);
                    }
                    // refill: slot (k&15) <- y[t0+k+16] (max idx 319 < 321)
                    w2h[ku] = yr[t0 + k + 16];
                }
            }

            #pragma unroll
            for (int i = 0; i < 16; i++) {
                float2 a = __half22float2(ta[i]);
                float2 bb = __half22float2(tb[i]);
                float iv = invn[t0 + i];       // 0 kills t >= TOUT / padding
                pe += fabsf(a.x + bb.x) * iv;
                po += fabsf(a.y + bb.y) * iv;
            }
        }

        atomicAdd(&sacc[2 * lane],     pe);
        atomicAdd(&sacc[2 * lane + 1], po);
    }

    __syncthreads();
    if (tid < 64) atomicAdd(&g_acc[b * F_ + 64 * h + tid], sacc[tid]);

    // ---- last-CTA finish: apply per-filter factors + bias; reset state ----
    __threadfence();
    __syncthreads();
    if (tid == 0) {
        unsigned old = atomicAdd(&g_count, 1u);
        sflag = (old == NCTA2_ - 1) ? 1u : 0u;
    }
    __syncthreads();
    if (sflag) {
        float* wf_s = (float*)sm2;   // reuse smem (yil region, done)
        if (tid < F_) {
            int f = tid;
            float sc = 0.f, ss = 0.f;
            #pragma unroll 8
            for (int k = 0; k < K_; k++) { float v = conv_w[f * K_ + k]; sc += v * v; }
            #pragma unroll 8
            for (int c = 0; c < CIN_; c++) { float v = spat_w[f * CIN_ + c]; ss += v * v; }
            // scale = sqrt(CIN*K) = 64 exactly; fold 1/Tout for the mean
            wf_s[f] = weight[f] * 64.0f / (sqrtf(sc) * sqrtf(ss) * (float)TOUT_);
        }
        __syncthreads();
        if (tid < B_) {
            float s = 0.f;
            #pragma unroll 8
            for (int f = 0; f < F_; f++)
                s += bias[f] + wf_s[f] * __ldcg(&g_acc[tid * F_ + f]);
            out[tid] = s;
        }
        __syncthreads();
        for (int i = tid; i < B_ * F_; i += 256) g_acc[i] = 0.f;
        if (tid == 0) g_count = 0u;
    }
}

// ---------------------------------------------------------------------------
extern "C" void kernel_launch(void* const* d_in, const int* in_sizes, int n_in,
                              void* d_out, int out_size) {
    const float* x      = (const float*)d_in[0];  // [64,64,4096]
    const float* conv_w = (const float*)d_in[1];  // [128,64]
    const float* spat_w = (const float*)d_in[2];  // [128,64]
    const float* weight = (const float*)d_in[3];  // [128]
    const float* bias   = (const float*)d_in[4];  // [128]
    float* out = (float*)d_out;                   // [64]

    cudaFuncSetAttribute(k1_spatial,
                         cudaFuncAttributeMaxDynamicSharedMemorySize, S1_BYTES);
    cudaFuncSetAttribute(k2_temporal,
                         cudaFuncAttributeMaxDynamicSharedMemorySize, SM2_BYTES);

    dim3 g1(NT1_, B_);
    k1_spatial<<<g1, 256, S1_BYTES>>>(x, spat_w);

    dim3 g2(NT2_, 2, B_);
    k2_temporal<<<g2, 256, SM2_BYTES>>>(conv_w, spat_w, weight, bias, out);
}

// round 17
// speedup vs baseline: 1.0373x; 1.0373x over previous
#include <cuda_runtime.h>
#include <cuda_fp16.h>
#include <cstdint>

// Problem constants
#define B_    64
#define CIN_  64
#define T_    4096
#define F_    128
#define K_    64
#define TOUT_ 4033
#define NPAIR 64
#define YROW  4160                // padded y row length (T_ + 64), pad stays zero
#define SROW  4160                // padded ssq row length

// ---- K1 (HMMA spatial GEMM) ----
#define T1_   128
#define NT1_  32                  // 4096 / 128
#define XFS   132                 // x_s fp32 row stride (floats)
#define HS    72                  // fp16 tile row stride (halves); 144B, 16B-aligned
#define S1_XF 0                   // x_s fp32: 64*132*4 = 33792 B
#define S1_W  33792               // Ws fp16: 128*72*2 = 18432 B
#define S1_X  52224               // Xs fp16: 128*72*2 = 18432 B
#define S1_BYTES 70656

// ---- K2 (temporal, fp32 FFMA2) ----
#define T2_   128
#define NT2_  32
#define NCTA2_ (NT2_ * 2 * B_)    // 4096
#define YIL2S 193                 // y tile row stride (float2)
#define CW2S  65                  // cw row stride (float2)
#define O2_Y    0                 // 32*193 f2 = 12352 floats
#define O2_CW   12352             // 32*65 f2 = 4160 floats
#define O2_SSQ  16512             // 192 (+pad)
#define O2_INV  16712             // 128
#define O2_SACC 16840             // 64
#define SM2_FLOATS 16912          // 67648 B -> 3 CTAs/SM

__device__ __align__(16) __half2 g_yh[(size_t)B_ * NPAIR * YROW];  // [b][pair][t]
__device__ float    g_ssq[B_ * SROW];
__device__ float    g_acc[B_ * F_];      // zero-init; reset by last CTA
__device__ unsigned g_count;             // zero-init; reset by last CTA

// ---------------------------------------------------------------------------
// Packed f32x2 FMA (SASS FFMA2 — only reachable via PTX)
// ---------------------------------------------------------------------------
__device__ __forceinline__ float2 ffma2(float2 a, float2 b, float2 c) {
    union U { float2 f; unsigned long long u; };
    U ua{a}, ub{b}, uc{c}, ur;
    asm("fma.rn.f32x2 %0, %1, %2, %3;" : "=l"(ur.u) : "l"(ua.u), "l"(ub.u), "l"(uc.u));
    return ur.f;
}

__device__ __forceinline__ uint32_t smem_u32(const void* p) {
    uint32_t a;
    asm("{ .reg .u64 t; cvta.to.shared.u64 t, %1; cvt.u32.u64 %0, t; }"
        : "=r"(a) : "l"(p));
    return a;
}

// ---------------------------------------------------------------------------
// K1: spatial GEMM on HMMA (mma.sync m16n8k16 f16 -> f32 acc) + exact ssq.
// grid (NT1_, B_), 256 threads. No OOB (32*128 = 4096 exact).
// ---------------------------------------------------------------------------
__global__ __launch_bounds__(256, 2)
void k1_spatial(const float* __restrict__ x,
                const float* __restrict__ spat_w) {
    extern __shared__ char smem[];
    float*   x_s = (float*)(smem + S1_XF);     // [64 c][XFS]
    __half2* ws2 = (__half2*)(smem + S1_W);    // [128 f][HS/2 half2]
    __half2* xs2 = (__half2*)(smem + S1_X);    // [128 t][HS/2 half2]
    const uint32_t wsb = smem_u32(smem + S1_W);
    const uint32_t xsb = smem_u32(smem + S1_X);

    const int tid  = threadIdx.x;
    const int b    = blockIdx.y;
    const int t0g  = blockIdx.x * T1_;
    const int warp = tid >> 5;
    const int lane = tid & 31;

    // ---- stage x fp32 tile [64c][128t] (coalesced float4) ----
    #pragma unroll
    for (int r = 0; r < 8; r++) {
        int q = r * 256 + tid;
        int c = q >> 5, t4 = (q & 31) * 4;
        *(float4*)(x_s + c * XFS + t4) =
            *(const float4*)(x + (size_t)(b * CIN_ + c) * T_ + t0g + t4);
    }
    // ---- stage W fp16: ws[f][c] ----
    #pragma unroll
    for (int r = 0; r < 16; r++) {
        int idx = r * 256 + tid;
        int f = idx >> 5, cp = idx & 31;
        float2 v = ((const float2*)spat_w)[idx];
        ws2[f * (HS / 2) + cp] = __floats2half2_rn(v.x, v.y);
    }
    __syncthreads();

    // ---- exact fp32 ssq ----
    if (tid < T1_) {
        float s = 0.f;
        #pragma unroll 8
        for (int c = 0; c < CIN_; c++) {
            float v = x_s[c * XFS + tid];
            s += v * v;
        }
        g_ssq[b * SROW + t0g + tid] = s;
    }
    // ---- transpose x -> Xs fp16 [t][c] ----
    {
        int t = tid & 127, ch = tid >> 7;
        int c0 = 32 * ch;
        #pragma unroll
        for (int j = 0; j < 16; j++) {
            float v0 = x_s[(c0 + 2 * j)     * XFS + t];
            float v1 = x_s[(c0 + 2 * j + 1) * XFS + t];
            xs2[t * (HS / 2) + c0 / 2 + j] = __floats2half2_rn(v0, v1);
        }
    }
    __syncthreads();

    // ---- HMMA: warp owns 16 filters x 128 t ----
    const int m0 = 16 * warp;
    float d[16][4];
    #pragma unroll
    for (int nt = 0; nt < 16; nt++)
        #pragma unroll
        for (int i = 0; i < 4; i++) d[nt][i] = 0.f;

    const int a_off = (m0 + (lane & 15)) * HS + (lane >> 4) * 8;
    const int b_off = (8 * (lane >> 4) + (lane & 7)) * HS + 8 * ((lane >> 3) & 1);

    #pragma unroll
    for (int ks = 0; ks < 4; ks++) {
        uint32_t a0, a1, a2, a3;
        {
            uint32_t addr = wsb + 2 * (a_off + 16 * ks);
            asm volatile("ldmatrix.sync.aligned.m8n8.x4.shared.b16 {%0,%1,%2,%3}, [%4];"
                : "=r"(a0), "=r"(a1), "=r"(a2), "=r"(a3) : "r"(addr));
        }
        #pragma unroll
        for (int j = 0; j < 8; j++) {
            uint32_t b0, b1, b2, b3;
            uint32_t addr = xsb + 2 * (b_off + (16 * j) * HS + 16 * ks);
            asm volatile("ldmatrix.sync.aligned.m8n8.x4.shared.b16 {%0,%1,%2,%3}, [%4];"
                : "=r"(b0), "=r"(b1), "=r"(b2), "=r"(b3) : "r"(addr));
            asm volatile(
                "mma.sync.aligned.m16n8k16.row.col.f32.f16.f16.f32 "
                "{%0,%1,%2,%3}, {%4,%5,%6,%7}, {%8,%9}, {%0,%1,%2,%3};"
                : "+f"(d[2*j][0]), "+f"(d[2*j][1]), "+f"(d[2*j][2]), "+f"(d[2*j][3])
                : "r"(a0), "r"(a1), "r"(a2), "r"(a3), "r"(b0), "r"(b1));
            asm volatile(
                "mma.sync.aligned.m16n8k16.row.col.f32.f16.f16.f32 "
                "{%0,%1,%2,%3}, {%4,%5,%6,%7}, {%8,%9}, {%0,%1,%2,%3};"
                : "+f"(d[2*j+1][0]), "+f"(d[2*j+1][1]), "+f"(d[2*j+1][2]), "+f"(d[2*j+1][3])
                : "r"(a0), "r"(a1), "r"(a2), "r"(a3), "r"(b2), "r"(b3));
        }
    }

    // ---- epilogue: pair even/odd filters via shfl, write half2 y ----
    {
        const int gid  = lane >> 2;
        const int tid4 = lane & 3;
        const bool wr  = (gid & 1) == 0;
        const size_t ybase = (size_t)b * NPAIR * YROW;
        const int Plo = 8 * warp + (gid >> 1);
        #pragma unroll
        for (int nt = 0; nt < 16; nt++) {
            float p0 = __shfl_xor_sync(0xffffffffu, d[nt][0], 4);
            float p1 = __shfl_xor_sync(0xffffffffu, d[nt][1], 4);
            float p2 = __shfl_xor_sync(0xffffffffu, d[nt][2], 4);
            float p3 = __shfl_xor_sync(0xffffffffu, d[nt][3], 4);
            if (wr) {
                int t = t0g + 8 * nt + 2 * tid4;
                __half2 h0 = __floats2half2_rn(d[nt][0], p0);
                __half2 h1 = __floats2half2_rn(d[nt][1], p1);
                __half2 h2 = __floats2half2_rn(d[nt][2], p2);
                __half2 h3 = __floats2half2_rn(d[nt][3], p3);
                float2 lo, hi;
                memcpy(&lo, &h0, 4); memcpy((char*)&lo + 4, &h1, 4);
                memcpy(&hi, &h2, 4); memcpy((char*)&hi + 4, &h3, 4);
                *(float2*)(g_yh + ybase + (size_t)Plo * YROW + t)       = lo;
                *(float2*)(g_yh + ybase + (size_t)(Plo + 4) * YROW + t) = hi;
            }
        }
    }
}

// ---------------------------------------------------------------------------
// K2: temporal conv (fp32 FFMA2) + reduction; guard-free vectorized staging.
// grid (NT2_, 2, B_), 256 threads, 3 CTAs/SM.
// ---------------------------------------------------------------------------
__global__ __launch_bounds__(256, 3)
void k2_temporal(const float* __restrict__ conv_w,
                 const float* __restrict__ spat_w,
                 const float* __restrict__ weight,
                 const float* __restrict__ bias,
                 float* __restrict__ out) {
    extern __shared__ float sm2[];
    float2* yil2 = (float2*)(sm2 + O2_Y);    // [32 pairs][YIL2S]
    float2* cw2  = (float2*)(sm2 + O2_CW);   // [32 pairs][CW2S]
    float*  ssqs = sm2 + O2_SSQ;             // [192]
    float*  invn = sm2 + O2_INV;             // [128]
    float*  sacc = sm2 + O2_SACC;            // [64]
    __shared__ unsigned sflag;

    const int tid  = threadIdx.x;
    const int tile = blockIdx.x;
    const int h    = blockIdx.y;             // filter half (64 filters)
    const int b    = blockIdx.z;
    const int t0g  = tile * T2_;
    const int warp = tid >> 5;
    const int lane = tid & 31;
    const int t0c  = 16 * warp;

    if (tid < 64) sacc[tid] = 0.f;

    // ---- stage y tile: 32 rows x 48 float4 (guard-free, pad is zero) ----
    {
        const __half2* ysrc = g_yh + (size_t)(b * NPAIR + 32 * h) * YROW + t0g;
        #pragma unroll
        for (int i = 0; i < 6; i++) {
            int idx = i * 256 + tid;         // 0..1535
            int p = idx / 48, q = idx - p * 48;
            float4 v = *(const float4*)(ysrc + (size_t)p * YROW + 4 * q);
            const __half2* hp = (const __half2*)&v;
            float2* dst = yil2 + p * YIL2S + 4 * q;
            dst[0] = __half22float2(hp[0]);
            dst[1] = __half22float2(hp[1]);
            dst[2] = __half22float2(hp[2]);
            dst[3] = __half22float2(hp[3]);
        }
    }
    // ---- stage interleaved conv weights from raw conv_w (coalesced LDG) ----
    #pragma unroll
    for (int r = 0; r < 16; r++) {
        int idx = r * 256 + tid;             // 0..4095
        int fl = idx >> 6, k = idx & 63;
        float v = conv_w[(64 * h + fl) * K_ + k];
        ((float*)cw2)[(fl >> 1) * (2 * CW2S) + 2 * k + (fl & 1)] = v;
    }
    // ---- stage ssq (guard-free, pad is zero) ----
    if (tid < 192) ssqs[tid] = g_ssq[b * SROW + t0g + tid];
    __syncthreads();

    if (tid < T2_) {
        float s = 0.f;
        #pragma unroll 8
        for (int k = 0; k < K_; k++) s += ssqs[tid + k];
        invn[tid] = ((t0g + tid) < TOUT_ && s > 0.f) ? rsqrtf(s) : 0.f;
    }
    __syncthreads();

    // ---- temporal conv: lane = pair, warp -> 16 t, modular 16-slot window ----
    {
        const float2* yr  = yil2 + lane * YIL2S;
        const float2* cwr = cw2 + lane * CW2S;

        float2 tacc[16];
        #pragma unroll
        for (int i = 0; i < 16; i++) tacc[i] = make_float2(0.f, 0.f);

        float2 w2[16];
        #pragma unroll
        for (int i = 0; i < 16; i++) w2[i] = yr[t0c + i];

        float2 s = cwr[0];                   // cw prefetch (1 k ahead)
        for (int ko = 0; ko < 4; ko++) {
            #pragma unroll
            for (int ku = 0; ku < 16; ku++) {
                const int k = 16 * ko + ku;
                float2 scur = s;
                s = cwr[k + 1];              // k=63 reads pad slot 64 (never used)
                #pragma unroll
                for (int i = 0; i < 16; i++)
                    tacc[i] = ffma2(scur, w2[(ku + i) & 15], tacc[i]);
                // refill: slot (k&15) <- y[t0c+k+16]  (max idx 191 < 193)
                w2[ku] = yr[t0c + k + 16];
            }
        }

        float pe = 0.f, po = 0.f;
        #pragma unroll
        for (int i = 0; i < 16; i++) {
            float iv = invn[t0c + i];   // 0 kills t >= TOUT and padded region
            pe += fabsf(tacc[i].x) * iv;
            po += fabsf(tacc[i].y) * iv;
        }
        atomicAdd(&sacc[2 * lane],     pe);
        atomicAdd(&sacc[2 * lane + 1], po);
    }

    __syncthreads();
    if (tid < 64) atomicAdd(&g_acc[b * F_ + 64 * h + tid], sacc[tid]);

    // ---- last-CTA finish: apply per-filter factors + bias; reset state ----
    __threadfence();
    __syncthreads();
    if (tid == 0) {
        unsigned old = atomicAdd(&g_count, 1u);
        sflag = (old == NCTA2_ - 1) ? 1u : 0u;
    }
    __syncthreads();
    if (sflag) {
        float* wf_s = sm2;   // reuse smem (yil region, done)
        if (tid < F_) {
            int f = tid;
            float sc = 0.f, ss = 0.f;
            #pragma unroll 8
            for (int k = 0; k < K_; k++) { float v = conv_w[f * K_ + k]; sc += v * v; }
            #pragma unroll 8
            for (int c = 0; c < CIN_; c++) { float v = spat_w[f * CIN_ + c]; ss += v * v; }
            // scale = sqrt(CIN*K) = 64 exactly; fold 1/Tout for the mean
            wf_s[f] = weight[f] * 64.0f / (sqrtf(sc) * sqrtf(ss) * (float)TOUT_);
        }
        __syncthreads();
        if (tid < B_) {
            float s = 0.f;
            #pragma unroll 8
            for (int f = 0; f < F_; f++)
                s += bias[f] + wf_s[f] * __ldcg(&g_acc[tid * F_ + f]);
            out[tid] = s;
        }
        __syncthreads();
        for (int i = tid; i < B_ * F_; i += 256) g_acc[i] = 0.f;
        if (tid == 0) g_count = 0u;
    }
}

// ---------------------------------------------------------------------------
extern "C" void kernel_launch(void* const* d_in, const int* in_sizes, int n_in,
                              void* d_out, int out_size) {
    const float* x      = (const float*)d_in[0];  // [64,64,4096]
    const float* conv_w = (const float*)d_in[1];  // [128,64]
    const float* spat_w = (const float*)d_in[2];  // [128,64]
    const float* weight = (const float*)d_in[3];  // [128]
    const float* bias   = (const float*)d_in[4];  // [128]
    float* out = (float*)d_out;                   // [64]

    cudaFuncSetAttribute(k1_spatial,
                         cudaFuncAttributeMaxDynamicSharedMemorySize, S1_BYTES);
    cudaFuncSetAttribute(k2_temporal,
                         cudaFuncAttributeMaxDynamicSharedMemorySize,
                         SM2_FLOATS * sizeof(float));

    dim3 g1(NT1_, B_);
    k1_spatial<<<g1, 256, S1_BYTES>>>(x, spat_w);

    dim3 g2(NT2_, 2, B_);
    k2_temporal<<<g2, 256, SM2_FLOATS * sizeof(float)>>>(
        conv_w, spat_w, weight, bias, out);
}